// round 3
// baseline (speedup 1.0000x reference)
#include <cuda_runtime.h>

// Problem shapes (fixed by reference): L=4, B=8, C=256, H=64, W=64
#define LN 4
#define BN 8
#define CN 256
#define HW 4096                 // 64*64, contiguous innermost per (l,b,c)
#define SLABS (LN * BN * CN)    // 8192
#define BH 4                    // half of B

// Scratch (no device allocation allowed)
__device__ float g_gap[SLABS];
__device__ float g_attn[SLABS];

// ---------------------------------------------------------------------------
// Kernel 1: GAP for one B-half. Grid = LN * BH * CN = 4096 blocks.
// One block per (l,b,c) slab of 4096 contiguous floats; 256 thr, 4x float4.
// Default cache policy: we WANT these lines resident in L2 for scale().
// ---------------------------------------------------------------------------
__global__ __launch_bounds__(256) void gap_kernel(const float* __restrict__ in,
                                                  int half) {
    const int id = blockIdx.x;                   // (l * BH + bb) * CN + c
    const int c  = id & (CN - 1);
    const int bb = (id >> 8) & (BH - 1);
    const int l  = id >> 10;
    const int b  = half * BH + bb;
    const int slab = (l * BN + b) * CN + c;

    const float4* p = reinterpret_cast<const float4*>(in + (size_t)slab * HW);
    const int tid = threadIdx.x;

    float s = 0.0f;
#pragma unroll
    for (int i = 0; i < 4; ++i) {
        float4 v = p[tid + i * 256];
        s += (v.x + v.y) + (v.z + v.w);
    }

#pragma unroll
    for (int off = 16; off > 0; off >>= 1)
        s += __shfl_down_sync(0xffffffffu, s, off);

    __shared__ float warp_s[8];
    if ((tid & 31) == 0) warp_s[tid >> 5] = s;
    __syncthreads();
    if (tid < 8) {
        float t = warp_s[tid];
#pragma unroll
        for (int off = 4; off > 0; off >>= 1)
            t += __shfl_down_sync(0xffu, t, off);
        if (tid == 0) g_gap[slab] = t * (1.0f / (float)HW);
    }
}

// ---------------------------------------------------------------------------
// Kernel 2: scores + softmax-over-L for one B-half. Grid = BH blocks.
// Thread = output channel d.
// ---------------------------------------------------------------------------
__global__ __launch_bounds__(256) void attn_kernel(const float* __restrict__ Wlin,
                                                   int half) {
    const int b = half * BH + blockIdx.x;
    const int d = threadIdx.x;

    __shared__ float g[LN][CN];
#pragma unroll
    for (int l = 0; l < LN; ++l)
        g[l][d] = g_gap[(l * BN + b) * CN + d];
    __syncthreads();

    const float4* wrow = reinterpret_cast<const float4*>(Wlin + (size_t)d * CN);
    float sc[LN] = {0.f, 0.f, 0.f, 0.f};
#pragma unroll 4
    for (int c4 = 0; c4 < CN / 4; ++c4) {
        float4 w = __ldg(&wrow[c4]);
        int c = c4 * 4;
#pragma unroll
        for (int l = 0; l < LN; ++l) {
            sc[l] += g[l][c + 0] * w.x;
            sc[l] += g[l][c + 1] * w.y;
            sc[l] += g[l][c + 2] * w.z;
            sc[l] += g[l][c + 3] * w.w;
        }
    }

    float m = sc[0];
#pragma unroll
    for (int l = 1; l < LN; ++l) m = fmaxf(m, sc[l]);
    float e[LN], sum = 0.f;
#pragma unroll
    for (int l = 0; l < LN; ++l) { e[l] = __expf(sc[l] - m); sum += e[l]; }
    float inv = 1.0f / sum;
#pragma unroll
    for (int l = 0; l < LN; ++l)
        g_attn[(l * BN + b) * CN + d] = e[l] * inv;
}

// ---------------------------------------------------------------------------
// Kernel 3: out = in * attn for one B-half. Grid = LN*BH*CN*4 = 16384 blocks.
// The chunk (67 MB) was just streamed by gap_kernel and is L2-resident.
// __ldcs: input line dead after this read. __stcs: output stores evict-first
// so they don't displace the resident input chunk.
// ---------------------------------------------------------------------------
__global__ __launch_bounds__(256) void scale_kernel(const float* __restrict__ in,
                                                    float* __restrict__ out,
                                                    int half) {
    const int blk  = blockIdx.x;                 // ((l*BH+bb)*CN + c)*4 + q
    const int q    = blk & 3;
    const int id   = blk >> 2;
    const int c  = id & (CN - 1);
    const int bb = (id >> 8) & (BH - 1);
    const int l  = id >> 10;
    const int b  = half * BH + bb;
    const int slab = (l * BN + b) * CN + c;

    const float a = __ldg(&g_attn[slab]);
    const size_t i4 = ((size_t)slab * 4 + q) * 256 + threadIdx.x;  // float4 units
    float4 v = __ldcs(reinterpret_cast<const float4*>(in) + i4);
    v.x *= a; v.y *= a; v.z *= a; v.w *= a;
    __stcs(reinterpret_cast<float4*>(out) + i4, v);
}

extern "C" void kernel_launch(void* const* d_in, const int* in_sizes, int n_in,
                              void* d_out, int out_size) {
    const float* in   = (const float*)d_in[0];   // [4,8,256,64,64]
    const float* Wlin = (const float*)d_in[1];   // [256,256]
    float* out = (float*)d_out;

    for (int h = 0; h < 2; ++h) {
        gap_kernel<<<LN * BH * CN, 256>>>(in, h);
        attn_kernel<<<BH, 256>>>(Wlin, h);
        scale_kernel<<<LN * BH * CN * 4, 256>>>(in, out, h);
    }
}

// round 4
// speedup vs baseline: 1.1621x; 1.1621x over previous
#include <cuda_runtime.h>

// Problem shapes (fixed by reference): L=4, B=8, C=256, H=64, W=64
#define LN 4
#define BN 8
#define CN 256
#define HW 4096                 // 64*64, contiguous innermost per (l,b,c)
#define SLABS (LN * BN * CN)    // 8192

// Scratch (no device allocation allowed)
__device__ float g_gap[SLABS];
__device__ float g_attn[SLABS];

// ---------------------------------------------------------------------------
// Kernel 1: GAP — one block per (l,b,c) slab of 4096 contiguous floats.
// 256 threads, 4 x float4 per thread. Default (allocating) loads: we WANT
// these lines resident in L2 for the scale pass.
// ---------------------------------------------------------------------------
__global__ __launch_bounds__(256) void gap_kernel(const float* __restrict__ in) {
    const int slab = blockIdx.x;
    const float4* p = reinterpret_cast<const float4*>(in + (size_t)slab * HW);
    const int tid = threadIdx.x;

    float s = 0.0f;
#pragma unroll
    for (int i = 0; i < 4; ++i) {
        float4 v = p[tid + i * 256];
        s += (v.x + v.y) + (v.z + v.w);
    }

#pragma unroll
    for (int off = 16; off > 0; off >>= 1)
        s += __shfl_down_sync(0xffffffffu, s, off);

    __shared__ float warp_s[8];
    if ((tid & 31) == 0) warp_s[tid >> 5] = s;
    __syncthreads();
    if (tid < 8) {
        float t = warp_s[tid];
#pragma unroll
        for (int off = 4; off > 0; off >>= 1)
            t += __shfl_down_sync(0xffu, t, off);
        if (tid == 0) g_gap[slab] = t * (1.0f / (float)HW);
    }
}

// ---------------------------------------------------------------------------
// Kernel 2: scores + softmax-over-L. Grid = B, thread = output channel d.
// ---------------------------------------------------------------------------
__global__ __launch_bounds__(256) void attn_kernel(const float* __restrict__ Wlin) {
    const int b = blockIdx.x;
    const int d = threadIdx.x;

    __shared__ float g[LN][CN];
#pragma unroll
    for (int l = 0; l < LN; ++l)
        g[l][d] = g_gap[(l * BN + b) * CN + d];
    __syncthreads();

    const float4* wrow = reinterpret_cast<const float4*>(Wlin + (size_t)d * CN);
    float sc[LN] = {0.f, 0.f, 0.f, 0.f};
#pragma unroll 4
    for (int c4 = 0; c4 < CN / 4; ++c4) {
        float4 w = __ldg(&wrow[c4]);
        int c = c4 * 4;
#pragma unroll
        for (int l = 0; l < LN; ++l) {
            sc[l] += g[l][c + 0] * w.x;
            sc[l] += g[l][c + 1] * w.y;
            sc[l] += g[l][c + 2] * w.z;
            sc[l] += g[l][c + 3] * w.w;
        }
    }

    float m = sc[0];
#pragma unroll
    for (int l = 1; l < LN; ++l) m = fmaxf(m, sc[l]);
    float e[LN], sum = 0.f;
#pragma unroll
    for (int l = 0; l < LN; ++l) { e[l] = __expf(sc[l] - m); sum += e[l]; }
    float inv = 1.0f / sum;
#pragma unroll
    for (int l = 0; l < LN; ++l)
        g_attn[(l * BN + b) * CN + d] = e[l] * inv;
}

// ---------------------------------------------------------------------------
// Kernel 3: out = in * attn, REVERSE slab order.
// gap_kernel streamed slabs 0..8191, so L2 holds the tail (~126 of 134 MB).
// Reverse order consumes the hottest lines first.
// __ldcs: input line dead after this read (evict-first).
// __stwt: WRITE-THROUGH stores — do NOT allocate in L2, so the 134 MB of
// output traffic cannot evict the resident input. This is the fix for the
// write-churn that defeated R2/R3.
// ---------------------------------------------------------------------------
__global__ __launch_bounds__(256) void scale_kernel(const float* __restrict__ in,
                                                    float* __restrict__ out) {
    const int blk  = (SLABS * 4 - 1) - blockIdx.x;   // reverse order
    const int slab = blk >> 2;
    const float a = __ldg(&g_attn[slab]);
    const size_t i4 = (size_t)blk * 256 + threadIdx.x;   // float4 units
    float4 v = __ldcs(reinterpret_cast<const float4*>(in) + i4);
    v.x *= a; v.y *= a; v.z *= a; v.w *= a;
    __stwt(reinterpret_cast<float4*>(out) + i4, v);
}

extern "C" void kernel_launch(void* const* d_in, const int* in_sizes, int n_in,
                              void* d_out, int out_size) {
    const float* in   = (const float*)d_in[0];   // [4,8,256,64,64]
    const float* Wlin = (const float*)d_in[1];   // [256,256]
    float* out = (float*)d_out;

    gap_kernel<<<SLABS, 256>>>(in);
    attn_kernel<<<BN, 256>>>(Wlin);
    scale_kernel<<<SLABS * 4, 256>>>(in, out);
}